// round 1
// baseline (speedup 1.0000x reference)
#include <cuda_runtime.h>
#include <math.h>

// ---------------------------------------------------------------------------
// ModelSpectral: hierarchical GraphSAGE + MLP + n x 2 Householder QR
// ---------------------------------------------------------------------------

#define N0 524288
#define E0 (N0 * 16)

// scratch (device globals; no allocations allowed)
__device__ float  g_bufA[N0 * 32];
__device__ float  g_bufB[N0 * 32];
__device__ int    g_rowptr[N0 + 1];
__device__ int    g_colidx[E0];
__device__ int    g_cnt[N0];
__device__ int    g_partials[512];
__device__ float  g_mat[N0 * 2];
__device__ double g_red[3];
__device__ double g_scal[6];

// ---------------------------------------------------------------------------
// coarsest level: x = eye(2), coarse_edges = [[0,1],[1,0]] (constant in setup)
// out[i][c] = tanh(Wc_l[1-i][c] + Wc_r[i][c] + bc[c]), written into bufA
// ---------------------------------------------------------------------------
__global__ void coarse_kernel(const float* __restrict__ Wcl,
                              const float* __restrict__ Wcr,
                              const float* __restrict__ bc) {
    int t = threadIdx.x;            // 64 threads
    int i = t >> 5, c = t & 31;
    g_bufA[t] = tanhf(Wcl[(1 - i) * 32 + c] + Wcr[i * 32 + c] + bc[c]);
}

// unpool: dst[i] = src[inv[i]]  (srcsel: 0 => src = A, write B; 1 => src = B)
__global__ void unpool_kernel(int srcsel, const int* __restrict__ inv, int n) {
    const float* src = srcsel ? g_bufB : g_bufA;
    float*       dst = srcsel ? g_bufA : g_bufB;
    int total = n * 32;
    for (int idx = blockIdx.x * blockDim.x + threadIdx.x; idx < total;
         idx += gridDim.x * blockDim.x) {
        int i = idx >> 5, j = idx & 31;
        dst[idx] = src[inv[i] * 32 + j];
    }
}

// ---------------------------------------------------------------------------
// CSR build (by destination)
// ---------------------------------------------------------------------------
__global__ void clear_cnt_kernel(int n) {
    for (int i = blockIdx.x * blockDim.x + threadIdx.x; i < n;
         i += gridDim.x * blockDim.x)
        g_cnt[i] = 0;
}

__global__ void count_kernel(const int* __restrict__ dst, int E) {
    for (int e = blockIdx.x * blockDim.x + threadIdx.x; e < E;
         e += gridDim.x * blockDim.x)
        atomicAdd(&g_cnt[dst[e]], 1);
}

// block-local exclusive scan (1024 items / block), block sums -> g_partials
__global__ void scan1_kernel(int n) {
    __shared__ int sm[256];
    int t = threadIdx.x;
    int base = blockIdx.x * 1024 + t * 4;
    int v[4];
#pragma unroll
    for (int i = 0; i < 4; i++) v[i] = (base + i < n) ? g_cnt[base + i] : 0;
    int s = v[0] + v[1] + v[2] + v[3];
    sm[t] = s;
    __syncthreads();
    for (int off = 1; off < 256; off <<= 1) {
        int y = (t >= off) ? sm[t - off] : 0;
        __syncthreads();
        sm[t] += y;
        __syncthreads();
    }
    int incl = sm[t];
    if (t == 255) g_partials[blockIdx.x] = incl;
    int run = incl - s;
#pragma unroll
    for (int i = 0; i < 4; i++) {
        if (base + i < n) g_rowptr[base + i] = run;
        run += v[i];
    }
}

// exclusive scan of block partials (nb <= 512), single block
__global__ void scan2_kernel(int nb) {
    __shared__ int sm[512];
    int t = threadIdx.x;
    int v = (t < nb) ? g_partials[t] : 0;
    sm[t] = v;
    __syncthreads();
    for (int off = 1; off < 512; off <<= 1) {
        int y = (t >= off) ? sm[t - off] : 0;
        __syncthreads();
        sm[t] += y;
        __syncthreads();
    }
    if (t < nb) g_partials[t] = sm[t] - v;
}

__global__ void scan3_kernel(int n, int E) {
    for (int i = blockIdx.x * blockDim.x + threadIdx.x; i < n;
         i += gridDim.x * blockDim.x)
        g_rowptr[i] += g_partials[i >> 10];
    if (blockIdx.x == 0 && threadIdx.x == 0) g_rowptr[n] = E;
}

__global__ void fill_kernel(const int* __restrict__ src,
                            const int* __restrict__ dst, int E) {
    for (int e = blockIdx.x * blockDim.x + threadIdx.x; e < E;
         e += gridDim.x * blockDim.x) {
        int d = dst[e];
        int p = g_rowptr[d] + atomicAdd(&g_cnt[d], 1);
        g_colidx[p] = src[e];
    }
}

// ---------------------------------------------------------------------------
// fused SAGEConv: y = tanh(mean_agg(x) @ Wl + x @ Wr + b)
// warp per node, lane = feature column; weights in registers, rows via smem
// srcsel: 0 => x = A, y = B ; 1 => x = B, y = A
// ---------------------------------------------------------------------------
__global__ void sage_conv_kernel(int srcsel, int n,
                                 const float* __restrict__ Wl,
                                 const float* __restrict__ Wr,
                                 const float* __restrict__ b) {
    const float* __restrict__ x = srcsel ? g_bufB : g_bufA;
    float* __restrict__ y       = srcsel ? g_bufA : g_bufB;

    int lane   = threadIdx.x & 31;
    int warp   = (blockIdx.x * blockDim.x + threadIdx.x) >> 5;
    int nwarps = (gridDim.x * blockDim.x) >> 5;
    int wloc   = threadIdx.x >> 5;

    float wl[32], wr[32];
#pragma unroll
    for (int k = 0; k < 32; k++) {
        wl[k] = Wl[k * 32 + lane];
        wr[k] = Wr[k * 32 + lane];
    }
    float bj = b[lane];

    __shared__ float sm[8][64];   // blockDim = 256 (8 warps)

    for (int i = warp; i < n; i += nwarps) {
        int r0 = g_rowptr[i], r1 = g_rowptr[i + 1];
        float a = 0.f;
        int k = r0;
        for (; k + 4 <= r1; k += 4) {
            int c0 = g_colidx[k], c1 = g_colidx[k + 1];
            int c2 = g_colidx[k + 2], c3 = g_colidx[k + 3];
            float f0 = x[c0 * 32 + lane];
            float f1 = x[c1 * 32 + lane];
            float f2 = x[c2 * 32 + lane];
            float f3 = x[c3 * 32 + lane];
            a += (f0 + f1) + (f2 + f3);
        }
        for (; k < r1; k++) a += x[g_colidx[k] * 32 + lane];

        int deg = r1 - r0;
        a *= 1.0f / (float)(deg > 0 ? deg : 1);
        float xj = x[i * 32 + lane];

        sm[wloc][lane]      = a;
        sm[wloc][32 + lane] = xj;
        __syncwarp();

        float acc = bj;
#pragma unroll
        for (int kk = 0; kk < 32; kk++) {
            acc += sm[wloc][kk] * wl[kk];
            acc += sm[wloc][32 + kk] * wr[kk];
        }
        y[i * 32 + lane] = tanhf(acc);
        __syncwarp();
    }
}

// ---------------------------------------------------------------------------
// MLP tail: 32 -> 16 -> 32 -> 32 -> 2 (tanh on first three), reads bufA
// ---------------------------------------------------------------------------
__global__ void mlp_kernel(int n,
                           const float* __restrict__ W1, const float* __restrict__ b1,
                           const float* __restrict__ W2, const float* __restrict__ b2,
                           const float* __restrict__ W3, const float* __restrict__ b3,
                           const float* __restrict__ Wf, const float* __restrict__ bf) {
    __shared__ float sW1[512], sW2[512], sW3[1024], sWf[64];
    __shared__ float sb1[16], sb2[32], sb3[32], sbf[2];
    int t = threadIdx.x;
    for (int i = t; i < 512; i += blockDim.x)  sW1[i] = W1[i];
    for (int i = t; i < 512; i += blockDim.x)  sW2[i] = W2[i];
    for (int i = t; i < 1024; i += blockDim.x) sW3[i] = W3[i];
    for (int i = t; i < 64; i += blockDim.x)   sWf[i] = Wf[i];
    if (t < 16) sb1[t] = b1[t];
    if (t < 32) sb2[t] = b2[t];
    if (t < 32) sb3[t] = b3[t];
    if (t < 2)  sbf[t] = bf[t];
    __syncthreads();

    for (int i = blockIdx.x * blockDim.x + t; i < n;
         i += gridDim.x * blockDim.x) {
        float h[32];
        const float4* xr = (const float4*)(g_bufA + i * 32);
#pragma unroll
        for (int q = 0; q < 8; q++) {
            float4 v = xr[q];
            h[q * 4] = v.x; h[q * 4 + 1] = v.y;
            h[q * 4 + 2] = v.z; h[q * 4 + 3] = v.w;
        }
        float t1[16];
#pragma unroll
        for (int j = 0; j < 16; j++) {
            float a = sb1[j];
#pragma unroll
            for (int k = 0; k < 32; k++) a += h[k] * sW1[k * 16 + j];
            t1[j] = tanhf(a);
        }
        float t2[32];
#pragma unroll
        for (int j = 0; j < 32; j++) {
            float a = sb2[j];
#pragma unroll
            for (int k = 0; k < 16; k++) a += t1[k] * sW2[k * 32 + j];
            t2[j] = tanhf(a);
        }
        float t3[32];
#pragma unroll
        for (int j = 0; j < 32; j++) {
            float a = sb3[j];
#pragma unroll
            for (int k = 0; k < 32; k++) a += t2[k] * sW3[k * 32 + j];
            t3[j] = tanhf(a);
        }
        float o0 = sbf[0], o1 = sbf[1];
#pragma unroll
        for (int k = 0; k < 32; k++) {
            o0 += t3[k] * sWf[k * 2];
            o1 += t3[k] * sWf[k * 2 + 1];
        }
        g_mat[i * 2]     = o0;
        g_mat[i * 2 + 1] = o1;
    }
}

// ---------------------------------------------------------------------------
// QR (n x 2) via LAPACK-convention Householder reflections
// ---------------------------------------------------------------------------
__global__ void clear_red_kernel() {
    g_red[0] = 0.0; g_red[1] = 0.0; g_red[2] = 0.0;
}

__global__ void qr_reduce_kernel(int n) {
    double s11 = 0, s12 = 0, s22 = 0;
    for (int i = blockIdx.x * blockDim.x + threadIdx.x; i < n;
         i += gridDim.x * blockDim.x) {
        double a = g_mat[2 * i], b = g_mat[2 * i + 1];
        s11 += a * a; s12 += a * b; s22 += b * b;
    }
#pragma unroll
    for (int off = 16; off; off >>= 1) {
        s11 += __shfl_down_sync(0xffffffffu, s11, off);
        s12 += __shfl_down_sync(0xffffffffu, s12, off);
        s22 += __shfl_down_sync(0xffffffffu, s22, off);
    }
    __shared__ double smr[3][8];
    int lane = threadIdx.x & 31, w = threadIdx.x >> 5;
    if (lane == 0) { smr[0][w] = s11; smr[1][w] = s12; smr[2][w] = s22; }
    __syncthreads();
    if (threadIdx.x == 0) {
        double a = 0, b = 0, c = 0;
        int nw = blockDim.x >> 5;
        for (int i = 0; i < nw; i++) { a += smr[0][i]; b += smr[1][i]; c += smr[2][i]; }
        atomicAdd(&g_red[0], a);
        atomicAdd(&g_red[1], b);
        atomicAdd(&g_red[2], c);
    }
}

__global__ void qr_scalars_kernel() {
    double s11 = g_red[0], s12 = g_red[1], s22 = g_red[2];
    double a10 = g_mat[0], a20 = g_mat[1];
    double a11 = g_mat[2], a21 = g_mat[3];
    // reflector 1 (LAPACK larfg convention: beta = -copysign(||a1||, a1[0]))
    double nrm1   = sqrt(s11);
    double beta1  = -copysign(nrm1, a10);
    double denom1 = a10 - beta1;
    double tau1   = (beta1 - a10) / beta1;
    double gg     = a20 + (s12 - a10 * a20) / denom1;   // v1^T a2
    double c20    = a20 - tau1 * gg;                    // (H1 a2)[0] = r12
    double v11    = a11 / denom1;
    double c21    = a21 - tau1 * v11 * gg;              // (H1 a2)[1]
    // reflector 2 on (H1 a2)[1:]
    double n2sq   = s22 - c20 * c20;
    if (n2sq < 0) n2sq = 0;
    double nrm2   = sqrt(n2sq);
    double beta2  = -copysign(nrm2, c21);
    double denom2 = c21 - beta2;
    double tau2   = (beta2 - c21) / beta2;
    // v1 . v2  (using v1^T c2 = -g since tau1 ||v1||^2 = 2)
    double v1v2 = v11 + (-gg - c20 - v11 * c21) / denom2;
    double w    = v11 - tau2 * v1v2;
    g_scal[0] = tau1;  g_scal[1] = 1.0 / denom1; g_scal[2] = gg;
    g_scal[3] = tau2;  g_scal[4] = 1.0 / denom2; g_scal[5] = w;
}

__global__ void qr_finalize_kernel(float* __restrict__ out, int n) {
    float tau1 = (float)g_scal[0], id1 = (float)g_scal[1], gg = (float)g_scal[2];
    float tau2 = (float)g_scal[3], id2 = (float)g_scal[4], w  = (float)g_scal[5];
    for (int j = blockIdx.x * blockDim.x + threadIdx.x; j < n;
         j += gridDim.x * blockDim.x) {
        float a1j = g_mat[2 * j], a2j = g_mat[2 * j + 1];
        float v1 = (j == 0) ? 1.f : a1j * id1;
        float c2 = a2j - tau1 * v1 * gg;
        float v2 = (j == 0) ? 0.f : ((j == 1) ? 1.f : c2 * id2);
        float q0 = -tau1 * v1;
        if (j == 0) q0 += 1.f;
        float q1 = -tau2 * v2 - tau1 * v1 * w;
        if (j == 1) q1 += 1.f;
        out[2 * j]     = q0;
        out[2 * j + 1] = q1;
    }
}

// ---------------------------------------------------------------------------
static inline int imin(int a, int b) { return a < b ? a : b; }

extern "C" void kernel_launch(void* const* d_in, const int* in_sizes, int n_in,
                              void* d_out, int out_size) {
    (void)in_sizes; (void)n_in; (void)out_size;
    static const int LS[7] = {524288, 65536, 8192, 1024, 128, 16, 2};

    const int* edges[6];
    const int* inv[6];
    for (int l = 0; l < 6; l++) {
        edges[l] = (const int*)d_in[2 * l];
        inv[l]   = (const int*)d_in[2 * l + 1];
    }
    // d_in[12] = coarse_edges (constant [[0,1],[1,0]], folded into coarse_kernel)
    const float* Wcl = (const float*)d_in[13];
    const float* Wcr = (const float*)d_in[14];
    const float* bc  = (const float*)d_in[15];
    const float* Wp_l[2] = {(const float*)d_in[16], (const float*)d_in[19]};
    const float* Wp_r[2] = {(const float*)d_in[17], (const float*)d_in[20]};
    const float* bp[2]   = {(const float*)d_in[18], (const float*)d_in[21]};
    const float* W1 = (const float*)d_in[22];
    const float* b1 = (const float*)d_in[23];
    const float* W2 = (const float*)d_in[24];
    const float* b2 = (const float*)d_in[25];
    const float* W3 = (const float*)d_in[26];
    const float* b3 = (const float*)d_in[27];
    const float* Wf = (const float*)d_in[28];
    const float* bf = (const float*)d_in[29];
    float* out = (float*)d_out;

    coarse_kernel<<<1, 64>>>(Wcl, Wcr, bc);

    int cur = 0;  // 0: current activations in bufA, 1: in bufB
    for (int l = 5; l >= 0; l--) {
        int n = LS[l];
        int E = n * 16;
        const int* esrc = edges[l];
        const int* edst = edges[l] + E;

        int tot = n * 32;
        unpool_kernel<<<imin((tot + 255) / 256, 4096), 256>>>(cur, inv[l], n);

        int cblocks = imin((n + 255) / 256, 2048);
        int eblocks = imin((E + 255) / 256, 4096);
        clear_cnt_kernel<<<cblocks, 256>>>(n);
        count_kernel<<<eblocks, 256>>>(edst, E);
        int nb = (n + 1023) / 1024;
        scan1_kernel<<<nb, 256>>>(n);
        scan2_kernel<<<1, 512>>>(nb);
        scan3_kernel<<<cblocks, 256>>>(n, E);
        clear_cnt_kernel<<<cblocks, 256>>>(n);
        fill_kernel<<<eblocks, 256>>>(esrc, edst, E);

        int wblocks = imin((n + 7) / 8, 2048);
        sage_conv_kernel<<<wblocks, 256>>>(cur ^ 1, n, Wp_l[0], Wp_r[0], bp[0]);
        sage_conv_kernel<<<wblocks, 256>>>(cur, n, Wp_l[1], Wp_r[1], bp[1]);
        cur ^= 1;
    }
    // after 6 levels cur == 0, activations in bufA

    int n0 = LS[0];
    mlp_kernel<<<2048, 256>>>(n0, W1, b1, W2, b2, W3, b3, Wf, bf);

    clear_red_kernel<<<1, 1>>>();
    qr_reduce_kernel<<<512, 256>>>(n0);
    qr_scalars_kernel<<<1, 1>>>();
    qr_finalize_kernel<<<2048, 256>>>(out, n0);
}